// round 4
// baseline (speedup 1.0000x reference)
#include <cuda_runtime.h>
#include <cuda_bf16.h>
#include <cstdint>

#define D 256
#define BM 128
#define BNT 128
#define LDS_ROW 264          // 256 + 8 bf16 pad -> conflict-free ldmatrix
#define MAXN_PAD 100352      // multiple of 128, >= 100000
#define MAXB 1024
#define NSPLIT 37            // 8 qblocks * 37 = 296 CTAs = 2 waves on 148 SMs
#define NTHREADS 512

#define TILE_BYTES_G (BNT * D * 2)            // 64 KB contiguous per tile in gmem
#define BUF_BYTES    (BM * LDS_ROW * 2)       // 67584 per smem buffer (padded rows)

__device__ __align__(256) __nv_bfloat16 g_tn[(size_t)MAXN_PAD * D];
__device__ __align__(256) __nv_bfloat16 g_qn[(size_t)MAXB * D];
__device__ float g_l[MAXB];
__device__ float g_s[MAXB];

// ---------------- tiny asm helpers ----------------

__device__ __forceinline__ void cp16(uint32_t dst, const void* src) {
    asm volatile("cp.async.cg.shared.global [%0], [%1], 16;" :: "r"(dst), "l"(src));
}
#define CP_COMMIT() asm volatile("cp.async.commit_group;" ::: "memory")
#define CP_WAIT1()  asm volatile("cp.async.wait_group 1;" ::: "memory")
#define CP_WAIT0()  asm volatile("cp.async.wait_group 0;" ::: "memory")

__device__ __forceinline__ float fsqrt_ap(float x) {
    float r; asm("sqrt.approx.f32 %0, %1;" : "=f"(r) : "f"(x)); return r;
}
__device__ __forceinline__ float fex2_ap(float x) {
    float r; asm("ex2.approx.f32 %0, %1;" : "=f"(r) : "f"(x)); return r;
}

// ---------------- prep kernels: L2-normalize into bf16 ----------------

__global__ void prep_q_kernel(const float* __restrict__ q, int B) {
    int gtid = blockIdx.x * blockDim.x + threadIdx.x;
    int row  = gtid >> 5;
    int lane = threadIdx.x & 31;
    if (gtid < MAXB) { g_l[gtid] = 0.f; g_s[gtid] = 0.f; }
    if (row >= B) return;
    const float* src = q + (size_t)row * D;
    float v[8], ss = 0.f;
#pragma unroll
    for (int i = 0; i < 8; i++) { v[i] = src[lane * 8 + i]; ss += v[i] * v[i]; }
#pragma unroll
    for (int o = 16; o > 0; o >>= 1) ss += __shfl_xor_sync(0xffffffffu, ss, o);
    float inv = 1.f / fmaxf(sqrtf(ss), 1e-12f);
    __nv_bfloat16* dst = g_qn + (size_t)row * D;
#pragma unroll
    for (int i = 0; i < 8; i++) dst[lane * 8 + i] = __float2bfloat16(v[i] * inv);
}

__global__ void prep_t_kernel(const float* __restrict__ t, int N, int Npad) {
    int gtid = blockIdx.x * blockDim.x + threadIdx.x;
    int row  = gtid >> 5;
    int lane = threadIdx.x & 31;
    if (row >= Npad) return;
    __nv_bfloat16* dst = g_tn + (size_t)row * D;
    if (row >= N) {
#pragma unroll
        for (int i = 0; i < 8; i++) dst[lane * 8 + i] = __float2bfloat16(0.f);
        return;
    }
    const float* src = t + (size_t)row * D;
    float v[8], ss = 0.f;
#pragma unroll
    for (int i = 0; i < 8; i++) { v[i] = src[lane * 8 + i]; ss += v[i] * v[i]; }
#pragma unroll
    for (int o = 16; o > 0; o >>= 1) ss += __shfl_xor_sync(0xffffffffu, ss, o);
    float inv = 1.f / fmaxf(sqrtf(ss), 1e-12f);
#pragma unroll
    for (int i = 0; i < 8; i++) dst[lane * 8 + i] = __float2bfloat16(v[i] * inv);
}

// ---------------- main kernel: pipelined GEMM + fused softmax-sum ----------------
// 16 warps: warp w -> rows (w>>2)*32 .. +32, cols (w&3)*32 .. +32

__global__ __launch_bounds__(NTHREADS, 1) void knn_main_kernel(int tilesTotal) {
    extern __shared__ unsigned char smem_raw[];
    __nv_bfloat16* Qs = (__nv_bfloat16*)smem_raw;
    __nv_bfloat16* Ts[2] = {
        (__nv_bfloat16*)(smem_raw + BUF_BYTES),
        (__nv_bfloat16*)(smem_raw + 2 * (size_t)BUF_BYTES)
    };
    float* sm_l = (float*)(smem_raw + 3 * (size_t)BUF_BYTES);
    float* sm_s = sm_l + BM;

    const int tid  = threadIdx.x;
    const int lane = tid & 31;
    const int warp = tid >> 5;
    const int wm   = warp >> 2;   // 0..3  -> 32-row slice
    const int wn   = warp & 3;    // 0..3  -> 32-col slice
    const int qb   = blockIdx.x;
    const int qbase = qb * BM;

    const int t0 = (int)(((long long)blockIdx.y       * tilesTotal) / gridDim.y);
    const int t1 = (int)(((long long)(blockIdx.y + 1) * tilesTotal) / gridDim.y);
    const int cnt = t1 - t0;

    const uint32_t TsAddr[2] = {
        (uint32_t)__cvta_generic_to_shared(Ts[0]),
        (uint32_t)__cvta_generic_to_shared(Ts[1])
    };

    // prologue: kick off tile t0 into buf 0 immediately (4096 chunks, 8/thread)
    if (cnt > 0) {
        const char* src = (const char*)g_tn + (size_t)t0 * TILE_BYTES_G;
#pragma unroll
        for (int i = 0; i < 8; i++) {
            int idx = tid + i * NTHREADS;
            int r = idx >> 5, c = idx & 31;
            cp16(TsAddr[0] + r * (LDS_ROW * 2) + c * 16, src + r * 512 + c * 16);
        }
        CP_COMMIT();
    }

    // Q block [128 x 256] -> smem (plain loads, once)
    {
        const uint4* src = (const uint4*)(g_qn + (size_t)qbase * D);
#pragma unroll
        for (int i = 0; i < 8; i++) {
            int idx = tid + i * NTHREADS;
            int r = idx >> 5, c8 = idx & 31;
            uint4 val = src[r * 32 + c8];
            *(uint4*)(Qs + r * LDS_ROW + c8 * 8) = val;
        }
    }
    if (tid < BM) { sm_l[tid] = 0.f; sm_s[tid] = 0.f; }

    float lrow[2][2], srow[2][2];
#pragma unroll
    for (int mi = 0; mi < 2; mi++) {
        lrow[mi][0] = lrow[mi][1] = 0.f;
        srow[mi][0] = srow[mi][1] = 0.f;
    }

    const uint32_t QsB = (uint32_t)__cvta_generic_to_shared(Qs);
    const int aRow  = lane & 15;
    const int aCoff = (lane >> 4) * 8;
    const int bRow  = lane & 7;
    const int bCoff = ((lane >> 3) & 1) * 8;

    for (int i = 0; i < cnt; i++) {
        const int s = i & 1;
        // issue next tile's copy into the other buffer (overlaps this tile's compute)
        if (i + 1 < cnt) {
            const char* src = (const char*)g_tn + (size_t)(t0 + i + 1) * TILE_BYTES_G;
            const uint32_t dstB = TsAddr[s ^ 1];
#pragma unroll
            for (int u = 0; u < 8; u++) {
                int idx = tid + u * NTHREADS;
                int r = idx >> 5, c = idx & 31;
                cp16(dstB + r * (LDS_ROW * 2) + c * 16, src + r * 512 + c * 16);
            }
            CP_COMMIT();
            CP_WAIT1();       // current tile's group done
        } else {
            CP_WAIT0();
        }
        __syncthreads();      // copies visible; prev compute done before buffer reuse

        const uint32_t TsB = TsAddr[s];
        float acc[2][4][4];
#pragma unroll
        for (int mi = 0; mi < 2; mi++)
#pragma unroll
            for (int ni = 0; ni < 4; ni++)
#pragma unroll
                for (int j = 0; j < 4; j++) acc[mi][ni][j] = 0.f;

#pragma unroll
        for (int ks = 0; ks < 16; ks++) {
            const int kk = ks * 16;
            uint32_t a[2][4];
#pragma unroll
            for (int mi = 0; mi < 2; mi++) {
                uint32_t addr = QsB + (uint32_t)(((wm * 32 + mi * 16 + aRow) * LDS_ROW + kk + aCoff) << 1);
                asm volatile("ldmatrix.sync.aligned.m8n8.x4.shared.b16 {%0,%1,%2,%3}, [%4];"
                             : "=r"(a[mi][0]), "=r"(a[mi][1]), "=r"(a[mi][2]), "=r"(a[mi][3])
                             : "r"(addr));
            }
            uint32_t b[4][2];
#pragma unroll
            for (int ni = 0; ni < 4; ni++) {
                uint32_t addr = TsB + (uint32_t)(((wn * 32 + ni * 8 + bRow) * LDS_ROW + kk + bCoff) << 1);
                asm volatile("ldmatrix.sync.aligned.m8n8.x2.shared.b16 {%0,%1}, [%2];"
                             : "=r"(b[ni][0]), "=r"(b[ni][1])
                             : "r"(addr));
            }
#pragma unroll
            for (int mi = 0; mi < 2; mi++)
#pragma unroll
                for (int ni = 0; ni < 4; ni++) {
                    asm volatile(
                        "mma.sync.aligned.m16n8k16.row.col.f32.bf16.bf16.f32 "
                        "{%0,%1,%2,%3}, {%4,%5,%6,%7}, {%8,%9}, {%0,%1,%2,%3};"
                        : "+f"(acc[mi][ni][0]), "+f"(acc[mi][ni][1]),
                          "+f"(acc[mi][ni][2]), "+f"(acc[mi][ni][3])
                        : "r"(a[mi][0]), "r"(a[mi][1]), "r"(a[mi][2]), "r"(a[mi][3]),
                          "r"(b[ni][0]), "r"(b[ni][1]));
                }
        }

        // Fused epilogue — no masking (pad rows handled analytically in finalize)
#pragma unroll
        for (int mi = 0; mi < 2; mi++)
#pragma unroll
            for (int ni = 0; ni < 4; ni++)
#pragma unroll
                for (int j = 0; j < 4; j++) {
                    float c  = acc[mi][ni][j];
                    float x  = fmaxf(fmaf(-2.f, c, 2.f), 0.f);
                    float dd = fsqrt_ap(x);
                    float e  = fex2_ap(dd * -14.4269504089f);   // exp(-10*d)
                    int   h  = j >> 1;
                    lrow[mi][h] += e;
                    srow[mi][h]  = fmaf(e, dd, srow[mi][h]);
                }
        __syncthreads();   // everyone done reading Ts[s] before it is refilled
    }

    // Reduce across the 4 lanes sharing a row, then smem, then global
#pragma unroll
    for (int mi = 0; mi < 2; mi++)
#pragma unroll
        for (int h = 0; h < 2; h++) {
            float lv = lrow[mi][h], sv = srow[mi][h];
            lv += __shfl_xor_sync(0xffffffffu, lv, 1);
            lv += __shfl_xor_sync(0xffffffffu, lv, 2);
            sv += __shfl_xor_sync(0xffffffffu, sv, 1);
            sv += __shfl_xor_sync(0xffffffffu, sv, 2);
            if ((lane & 3) == 0) {
                int r = wm * 32 + mi * 16 + (lane >> 2) + 8 * h;
                atomicAdd(&sm_l[r], lv);
                atomicAdd(&sm_s[r], sv);
            }
        }
    __syncthreads();
    if (tid < BM) {
        atomicAdd(&g_l[qbase + tid], sm_l[tid]);
        atomicAdd(&g_s[qbase + tid], sm_s[tid]);
    }
}

__global__ void finalize_kernel(float* __restrict__ out, int B, int padCount) {
    int i = blockIdx.x * blockDim.x + threadIdx.x;
    if (i >= B) return;
    // pad rows contribute c=0 -> d0 = sqrt.approx(2), e0 = ex2.approx(-10*d0*log2e)
    float d0 = fsqrt_ap(2.0f);
    float e0 = fex2_ap(d0 * -14.4269504089f);
    float fp = (float)padCount;
    out[i] = (g_s[i] - fp * e0 * d0) / (g_l[i] - fp * e0);
}

// ---------------- launch ----------------

extern "C" void kernel_launch(void* const* d_in, const int* in_sizes, int n_in,
                              void* d_out, int out_size) {
    const float* q = (const float*)d_in[0];
    const float* t = (const float*)d_in[1];
    int B = in_sizes[0] / D;
    int N = in_sizes[1] / D;
    if (B > MAXB) B = MAXB;
    int Npad = ((N + BNT - 1) / BNT) * BNT;
    if (Npad > MAXN_PAD) Npad = MAXN_PAD;
    int tilesTotal = Npad / BNT;
    int padCount = tilesTotal * BNT - N;

    const int smemBytes = 3 * BUF_BYTES + 2 * BM * (int)sizeof(float);
    cudaFuncSetAttribute(knn_main_kernel,
                         cudaFuncAttributeMaxDynamicSharedMemorySize, smemBytes);

    prep_q_kernel<<<(B * 32 + 255) / 256, 256>>>(q, B);
    prep_t_kernel<<<(Npad * 32 + 255) / 256, 256>>>(t, N, Npad);

    int numQB = B / BM;
    if (numQB < 1) numQB = 1;
    knn_main_kernel<<<dim3(numQB, NSPLIT), NTHREADS, smemBytes>>>(tilesTotal);

    finalize_kernel<<<(B + 255) / 256, 256>>>((float*)d_out, B, padCount);
}

// round 6
// speedup vs baseline: 1.0449x; 1.0449x over previous
#include <cuda_runtime.h>
#include <cuda_bf16.h>
#include <cstdint>

#define D 256
#define BM 128
#define BNT 128
#define LDS_ROW 264          // 256 + 8 bf16 pad -> conflict-free ldmatrix
#define MAXN_PAD 100352      // multiple of 128, >= 100000
#define MAXB 1024
#define NSPLIT 37            // 8 qblocks * 37 = 296 CTAs = 2 waves on 148 SMs
#define NTHREADS 512

#define TILE_BYTES_G (BNT * D * 2)            // 64 KB contiguous per tile in gmem
#define BUF_BYTES    (BM * LDS_ROW * 2)       // 67584 per smem buffer (padded rows)

__device__ __align__(256) __nv_bfloat16 g_tn[(size_t)MAXN_PAD * D];
__device__ __align__(256) __nv_bfloat16 g_qn[(size_t)MAXB * D];
__device__ float g_l[MAXB];
__device__ float g_s[MAXB];

// ---------------- tiny asm helpers ----------------

__device__ __forceinline__ void cp16(uint32_t dst, const void* src) {
    asm volatile("cp.async.cg.shared.global [%0], [%1], 16;" :: "r"(dst), "l"(src));
}
#define CP_COMMIT() asm volatile("cp.async.commit_group;" ::: "memory")
#define CP_WAIT1()  asm volatile("cp.async.wait_group 1;" ::: "memory")
#define CP_WAIT0()  asm volatile("cp.async.wait_group 0;" ::: "memory")

__device__ __forceinline__ float fsqrt_ap(float x) {
    float r; asm("sqrt.approx.f32 %0, %1;" : "=f"(r) : "f"(x)); return r;
}
__device__ __forceinline__ float fex2_ap(float x) {
    float r; asm("ex2.approx.f32 %0, %1;" : "=f"(r) : "f"(x)); return r;
}

// ---------------- prep kernels: L2-normalize into bf16 ----------------

__global__ void prep_q_kernel(const float* __restrict__ q, int B) {
    int gtid = blockIdx.x * blockDim.x + threadIdx.x;
    int row  = gtid >> 5;
    int lane = threadIdx.x & 31;
    if (gtid < MAXB) { g_l[gtid] = 0.f; g_s[gtid] = 0.f; }
    if (row >= B) return;
    const float* src = q + (size_t)row * D;
    float v[8], ss = 0.f;
#pragma unroll
    for (int i = 0; i < 8; i++) { v[i] = src[lane * 8 + i]; ss += v[i] * v[i]; }
#pragma unroll
    for (int o = 16; o > 0; o >>= 1) ss += __shfl_xor_sync(0xffffffffu, ss, o);
    float inv = 1.f / fmaxf(sqrtf(ss), 1e-12f);
    __nv_bfloat16* dst = g_qn + (size_t)row * D;
#pragma unroll
    for (int i = 0; i < 8; i++) dst[lane * 8 + i] = __float2bfloat16(v[i] * inv);
}

__global__ void prep_t_kernel(const float* __restrict__ t, int N, int Npad) {
    int gtid = blockIdx.x * blockDim.x + threadIdx.x;
    int row  = gtid >> 5;
    int lane = threadIdx.x & 31;
    if (row >= Npad) return;
    __nv_bfloat16* dst = g_tn + (size_t)row * D;
    if (row >= N) {
#pragma unroll
        for (int i = 0; i < 8; i++) dst[lane * 8 + i] = __float2bfloat16(0.f);
        return;
    }
    const float* src = t + (size_t)row * D;
    float v[8], ss = 0.f;
#pragma unroll
    for (int i = 0; i < 8; i++) { v[i] = src[lane * 8 + i]; ss += v[i] * v[i]; }
#pragma unroll
    for (int o = 16; o > 0; o >>= 1) ss += __shfl_xor_sync(0xffffffffu, ss, o);
    float inv = 1.f / fmaxf(sqrtf(ss), 1e-12f);
#pragma unroll
    for (int i = 0; i < 8; i++) dst[lane * 8 + i] = __float2bfloat16(v[i] * inv);
}

// ---------------- main kernel ----------------
// 16 warps; warp tile 16 rows x 64 cols. A (Q) hoisted to registers once.
// 3-stage cp.async T ring; Q staged through buf2 then overwritten.

__global__ __launch_bounds__(NTHREADS, 1) void knn_main_kernel(int tilesTotal) {
    extern __shared__ unsigned char smem_raw[];
    float* sm_l = (float*)(smem_raw + 3 * (size_t)BUF_BYTES);
    float* sm_s = sm_l + BM;

    const int tid  = threadIdx.x;
    const int lane = tid & 31;
    const int warp = tid >> 5;
    const int wm   = warp >> 1;   // 0..7  -> 16-row slice
    const int wn   = warp & 1;    // 0..1  -> 64-col slice
    const int qb   = blockIdx.x;
    const int qbase = qb * BM;

    const int t0 = (int)(((long long)blockIdx.y       * tilesTotal) / gridDim.y);
    const int t1 = (int)(((long long)(blockIdx.y + 1) * tilesTotal) / gridDim.y);
    const int cnt = t1 - t0;

    const uint32_t smemB = (uint32_t)__cvta_generic_to_shared(smem_raw);
    const uint32_t bufA[3] = { smemB, smemB + BUF_BYTES, smemB + 2u * BUF_BYTES };

    // prologue: kick tiles t0 -> buf0, t0+1 -> buf1
#pragma unroll
    for (int p = 0; p < 2; p++) {
        if (p < cnt) {
            const char* src = (const char*)g_tn + (size_t)(t0 + p) * TILE_BYTES_G;
#pragma unroll
            for (int i = 0; i < 8; i++) {
                int idx = tid + i * NTHREADS;
                int r = idx >> 5, c = idx & 31;
                cp16(bufA[p] + r * (LDS_ROW * 2) + c * 16, src + r * 512 + c * 16);
            }
            CP_COMMIT();
        }
    }

    // Q block -> buf2 (staging), then hoist A fragments to registers
    {
        const uint4* src = (const uint4*)(g_qn + (size_t)qbase * D);
        __nv_bfloat16* Qs = (__nv_bfloat16*)(smem_raw + 2 * (size_t)BUF_BYTES);
#pragma unroll
        for (int i = 0; i < 8; i++) {
            int idx = tid + i * NTHREADS;
            int r = idx >> 5, c8 = idx & 31;
            uint4 val = src[r * 32 + c8];
            *(uint4*)(Qs + r * LDS_ROW + c8 * 8) = val;
        }
    }
    if (tid < BM) { sm_l[tid] = 0.f; sm_s[tid] = 0.f; }
    __syncthreads();

    uint32_t Areg[16][4];
    {
        const int aRow  = lane & 15;
        const int aCoff = (lane >> 4) * 8;
        const uint32_t aBase = bufA[2] +
            (uint32_t)(((wm * 16 + aRow) * LDS_ROW + aCoff) << 1);
#pragma unroll
        for (int ks = 0; ks < 16; ks++) {
            asm volatile("ldmatrix.sync.aligned.m8n8.x4.shared.b16 {%0,%1,%2,%3}, [%4];"
                         : "=r"(Areg[ks][0]), "=r"(Areg[ks][1]),
                           "=r"(Areg[ks][2]), "=r"(Areg[ks][3])
                         : "r"(aBase + (uint32_t)(ks * 32)));
        }
    }

    float lrow[2] = {0.f, 0.f}, srow[2] = {0.f, 0.f};

    // B ldmatrix x4 addressing: two n8 tiles per load
    const int bR = (lane & 7) + ((lane >> 4) << 3);   // n offset within 16-row pair
    const int bC = ((lane >> 3) & 1) << 3;            // k offset
    const uint32_t bThread = (uint32_t)(((wn * 64 + bR) * LDS_ROW + bC) << 1);

    for (int i = 0; i < cnt; i++) {
        if (i + 1 < cnt) { CP_WAIT1(); } else { CP_WAIT0(); }
        __syncthreads();   // tile i visible to all; all warps done reading buf (i-1)%3

        // prefetch tile i+2 into buf (i+2)%3 (== buf (i-1)%3, just released)
        if (i + 2 < cnt) {
            const char* src = (const char*)g_tn + (size_t)(t0 + i + 2) * TILE_BYTES_G;
            const uint32_t dstB = bufA[(i + 2) % 3];
#pragma unroll
            for (int u = 0; u < 8; u++) {
                int idx = tid + u * NTHREADS;
                int r = idx >> 5, c = idx & 31;
                cp16(dstB + r * (LDS_ROW * 2) + c * 16, src + r * 512 + c * 16);
            }
            CP_COMMIT();
        }

        const uint32_t TsB = bufA[i % 3] + bThread;

        float acc[8][4];
#pragma unroll
        for (int nt = 0; nt < 8; nt++)
#pragma unroll
            for (int j = 0; j < 4; j++) acc[nt][j] = 0.f;

#pragma unroll
        for (int ks = 0; ks < 16; ks++) {
            const uint32_t kOff = (uint32_t)(ks * 32);
#pragma unroll
            for (int np = 0; np < 4; np++) {    // pair of n8 tiles per ldmatrix x4
                uint32_t b0, b1, b2, b3;
                uint32_t addr = TsB + (uint32_t)(np * 16 * LDS_ROW * 2) + kOff;
                asm volatile("ldmatrix.sync.aligned.m8n8.x4.shared.b16 {%0,%1,%2,%3}, [%4];"
                             : "=r"(b0), "=r"(b1), "=r"(b2), "=r"(b3)
                             : "r"(addr));
                asm volatile(
                    "mma.sync.aligned.m16n8k16.row.col.f32.bf16.bf16.f32 "
                    "{%0,%1,%2,%3}, {%4,%5,%6,%7}, {%8,%9}, {%0,%1,%2,%3};"
                    : "+f"(acc[2*np][0]), "+f"(acc[2*np][1]),
                      "+f"(acc[2*np][2]), "+f"(acc[2*np][3])
                    : "r"(Areg[ks][0]), "r"(Areg[ks][1]),
                      "r"(Areg[ks][2]), "r"(Areg[ks][3]),
                      "r"(b0), "r"(b1));
                asm volatile(
                    "mma.sync.aligned.m16n8k16.row.col.f32.bf16.bf16.f32 "
                    "{%0,%1,%2,%3}, {%4,%5,%6,%7}, {%8,%9}, {%0,%1,%2,%3};"
                    : "+f"(acc[2*np+1][0]), "+f"(acc[2*np+1][1]),
                      "+f"(acc[2*np+1][2]), "+f"(acc[2*np+1][3])
                    : "r"(Areg[ks][0]), "r"(Areg[ks][1]),
                      "r"(Areg[ks][2]), "r"(Areg[ks][3]),
                      "r"(b2), "r"(b3));
            }
        }

        // Fused epilogue — no masking (pad rows handled analytically in finalize)
#pragma unroll
        for (int nt = 0; nt < 8; nt++)
#pragma unroll
            for (int j = 0; j < 4; j++) {
                float c  = acc[nt][j];
                float x  = fmaxf(fmaf(-2.f, c, 2.f), 0.f);
                float dd = fsqrt_ap(x);
                float e  = fex2_ap(dd * -14.4269504089f);   // exp(-10*d)
                int   h  = j >> 1;
                lrow[h] += e;
                srow[h]  = fmaf(e, dd, srow[h]);
            }
    }

    // Reduce across the 4 lanes sharing a row, then smem, then global
#pragma unroll
    for (int h = 0; h < 2; h++) {
        float lv = lrow[h], sv = srow[h];
        lv += __shfl_xor_sync(0xffffffffu, lv, 1);
        lv += __shfl_xor_sync(0xffffffffu, lv, 2);
        sv += __shfl_xor_sync(0xffffffffu, sv, 1);
        sv += __shfl_xor_sync(0xffffffffu, sv, 2);
        if ((lane & 3) == 0) {
            int r = wm * 16 + (lane >> 2) + 8 * h;
            atomicAdd(&sm_l[r], lv);
            atomicAdd(&sm_s[r], sv);
        }
    }
    __syncthreads();
    if (tid < BM) {
        atomicAdd(&g_l[qbase + tid], sm_l[tid]);
        atomicAdd(&g_s[qbase + tid], sm_s[tid]);
    }
}

__global__ void finalize_kernel(float* __restrict__ out, int B, int padCount) {
    int i = blockIdx.x * blockDim.x + threadIdx.x;
    if (i >= B) return;
    // pad rows contribute c=0 -> d0 = sqrt.approx(2), e0 = ex2.approx(-10*d0*log2e)
    float d0 = fsqrt_ap(2.0f);
    float e0 = fex2_ap(d0 * -14.4269504089f);
    float fp = (float)padCount;
    out[i] = (g_s[i] - fp * e0 * d0) / (g_l[i] - fp * e0);
}

// ---------------- launch ----------------

extern "C" void kernel_launch(void* const* d_in, const int* in_sizes, int n_in,
                              void* d_out, int out_size) {
    const float* q = (const float*)d_in[0];
    const float* t = (const float*)d_in[1];
    int B = in_sizes[0] / D;
    int N = in_sizes[1] / D;
    if (B > MAXB) B = MAXB;
    int Npad = ((N + BNT - 1) / BNT) * BNT;
    if (Npad > MAXN_PAD) Npad = MAXN_PAD;
    int tilesTotal = Npad / BNT;
    int padCount = tilesTotal * BNT - N;

    const int smemBytes = 3 * BUF_BYTES + 2 * BM * (int)sizeof(float);
    cudaFuncSetAttribute(knn_main_kernel,
                         cudaFuncAttributeMaxDynamicSharedMemorySize, smemBytes);

    prep_q_kernel<<<(B * 32 + 255) / 256, 256>>>(q, B);
    prep_t_kernel<<<(Npad * 32 + 255) / 256, 256>>>(t, N, Npad);

    int numQB = B / BM;
    if (numQB < 1) numQB = 1;
    knn_main_kernel<<<dim3(numQB, NSPLIT), NTHREADS, smemBytes>>>(tilesTotal);

    finalize_kernel<<<(B + 255) / 256, 256>>>((float*)d_out, B, padCount);
}

// round 7
// speedup vs baseline: 1.1543x; 1.1047x over previous
#include <cuda_runtime.h>
#include <cuda_bf16.h>
#include <cstdint>

#define D 256
#define BM 128
#define BNT 64               // T tile rows (n) per iteration
#define LDS_ROW 264          // 256 + 8 bf16 pad -> conflict-free ldmatrix
#define MAXN_PAD 100032      // multiple of 64, >= 100000
#define MAXB 1024
#define NSPLIT 37            // 8 qblocks * 37 = 296 CTAs = 2 CTAs/SM, one wave
#define NTHREADS 256

#define TILE_BYTES_G (BNT * D * 2)            // 32 KB contiguous per tile in gmem
#define BUF_BYTES    (BNT * LDS_ROW * 2)      // 33792 per smem buffer (padded rows)

__device__ __align__(256) __nv_bfloat16 g_tn[(size_t)MAXN_PAD * D];
__device__ __align__(256) __nv_bfloat16 g_qn[(size_t)MAXB * D];
__device__ float g_l[MAXB];
__device__ float g_s[MAXB];

// ---------------- tiny asm helpers ----------------

__device__ __forceinline__ void cp16(uint32_t dst, const void* src) {
    asm volatile("cp.async.cg.shared.global [%0], [%1], 16;" :: "r"(dst), "l"(src));
}
#define CP_COMMIT() asm volatile("cp.async.commit_group;" ::: "memory")
#define CP_WAIT1()  asm volatile("cp.async.wait_group 1;" ::: "memory")
#define CP_WAIT0()  asm volatile("cp.async.wait_group 0;" ::: "memory")

__device__ __forceinline__ float fsqrt_ap(float x) {
    float r; asm("sqrt.approx.f32 %0, %1;" : "=f"(r) : "f"(x)); return r;
}
__device__ __forceinline__ float fex2_ap(float x) {
    float r; asm("ex2.approx.f32 %0, %1;" : "=f"(r) : "f"(x)); return r;
}

// ---------------- prep kernels: L2-normalize into bf16 ----------------

__global__ void prep_q_kernel(const float* __restrict__ q, int B) {
    int gtid = blockIdx.x * blockDim.x + threadIdx.x;
    int row  = gtid >> 5;
    int lane = threadIdx.x & 31;
    if (gtid < MAXB) { g_l[gtid] = 0.f; g_s[gtid] = 0.f; }
    if (row >= B) return;
    const float* src = q + (size_t)row * D;
    float v[8], ss = 0.f;
#pragma unroll
    for (int i = 0; i < 8; i++) { v[i] = src[lane * 8 + i]; ss += v[i] * v[i]; }
#pragma unroll
    for (int o = 16; o > 0; o >>= 1) ss += __shfl_xor_sync(0xffffffffu, ss, o);
    float inv = 1.f / fmaxf(sqrtf(ss), 1e-12f);
    __nv_bfloat16* dst = g_qn + (size_t)row * D;
#pragma unroll
    for (int i = 0; i < 8; i++) dst[lane * 8 + i] = __float2bfloat16(v[i] * inv);
}

__global__ void prep_t_kernel(const float* __restrict__ t, int N, int Npad) {
    int gtid = blockIdx.x * blockDim.x + threadIdx.x;
    int row  = gtid >> 5;
    int lane = threadIdx.x & 31;
    if (row >= Npad) return;
    __nv_bfloat16* dst = g_tn + (size_t)row * D;
    if (row >= N) {
#pragma unroll
        for (int i = 0; i < 8; i++) dst[lane * 8 + i] = __float2bfloat16(0.f);
        return;
    }
    const float* src = t + (size_t)row * D;
    float v[8], ss = 0.f;
#pragma unroll
    for (int i = 0; i < 8; i++) { v[i] = src[lane * 8 + i]; ss += v[i] * v[i]; }
#pragma unroll
    for (int o = 16; o > 0; o >>= 1) ss += __shfl_xor_sync(0xffffffffu, ss, o);
    float inv = 1.f / fmaxf(sqrtf(ss), 1e-12f);
#pragma unroll
    for (int i = 0; i < 8; i++) dst[lane * 8 + i] = __float2bfloat16(v[i] * inv);
}

// ---------------- main kernel ----------------
// 8 warps; warp tile 16 rows x 64 cols (full BNT width). A (Q) in registers.
// 3-stage cp.async T ring (BNT=64); Q staged through buf0+buf1 then overwritten.
// 2 CTAs/SM -> phase-independent CTAs overlap HMMA and MUFU pipes.

__global__ __launch_bounds__(NTHREADS, 2) void knn_main_kernel(int tilesTotal) {
    extern __shared__ unsigned char smem_raw[];

    const int tid  = threadIdx.x;
    const int lane = tid & 31;
    const int warp = tid >> 5;
    const int wm   = warp;        // 0..7 -> 16-row slice of the 128 query rows
    const int qb   = blockIdx.x;
    const int qbase = qb * BM;

    const int t0 = (int)(((long long)blockIdx.y       * tilesTotal) / gridDim.y);
    const int t1 = (int)(((long long)(blockIdx.y + 1) * tilesTotal) / gridDim.y);
    const int cnt = t1 - t0;

    const uint32_t smemB = (uint32_t)__cvta_generic_to_shared(smem_raw);
    const uint32_t bufA[3] = { smemB, smemB + BUF_BYTES, smemB + 2u * BUF_BYTES };

    // ---- stage Q [128 x 256] into buf0+buf1 (exactly 2 buffers), hoist A ----
    {
        const uint4* src = (const uint4*)(g_qn + (size_t)qbase * D);
        __nv_bfloat16* Qs = (__nv_bfloat16*)smem_raw;
#pragma unroll
        for (int i = 0; i < 16; i++) {
            int idx = tid + i * NTHREADS;         // 4096 chunks of 16B
            int r = idx >> 5, c8 = idx & 31;
            uint4 val = src[r * 32 + c8];
            *(uint4*)(Qs + r * LDS_ROW + c8 * 8) = val;
        }
    }
    __syncthreads();

    uint32_t Areg[16][4];
    {
        const int aRow  = lane & 15;
        const int aCoff = (lane >> 4) * 8;
        const uint32_t aBase = smemB +
            (uint32_t)(((wm * 16 + aRow) * LDS_ROW + aCoff) << 1);
#pragma unroll
        for (int ks = 0; ks < 16; ks++) {
            asm volatile("ldmatrix.sync.aligned.m8n8.x4.shared.b16 {%0,%1,%2,%3}, [%4];"
                         : "=r"(Areg[ks][0]), "=r"(Areg[ks][1]),
                           "=r"(Areg[ks][2]), "=r"(Areg[ks][3])
                         : "r"(aBase + (uint32_t)(ks * 32)));
        }
    }
    __syncthreads();   // all hoists done before T copies overwrite staging

    // ---- prologue: kick tiles t0 -> buf0, t0+1 -> buf1 ----
#pragma unroll
    for (int p = 0; p < 2; p++) {
        if (p < cnt) {
            const char* src = (const char*)g_tn + (size_t)(t0 + p) * TILE_BYTES_G;
#pragma unroll
            for (int i = 0; i < 8; i++) {
                int idx = tid + i * NTHREADS;     // 2048 chunks of 16B
                int r = idx >> 5, c = idx & 31;
                cp16(bufA[p] + r * (LDS_ROW * 2) + c * 16, src + r * 512 + c * 16);
            }
            CP_COMMIT();
        }
    }

    float lrow[2] = {0.f, 0.f}, srow[2] = {0.f, 0.f};

    // B ldmatrix x4 addressing: two n8 tiles (16 rows) per load
    const int bR = (lane & 7) + ((lane >> 4) << 3);
    const int bC = ((lane >> 3) & 1) << 3;
    const uint32_t bThread = (uint32_t)((bR * LDS_ROW + bC) << 1);

    for (int i = 0; i < cnt; i++) {
        if (i + 1 < cnt) { CP_WAIT1(); } else { CP_WAIT0(); }
        __syncthreads();   // tile i visible; all warps done with buf (i-1)%3

        // prefetch tile i+2 into the just-released buffer
        if (i + 2 < cnt) {
            const char* src = (const char*)g_tn + (size_t)(t0 + i + 2) * TILE_BYTES_G;
            const uint32_t dstB = bufA[(i + 2) % 3];
#pragma unroll
            for (int u = 0; u < 8; u++) {
                int idx = tid + u * NTHREADS;
                int r = idx >> 5, c = idx & 31;
                cp16(dstB + r * (LDS_ROW * 2) + c * 16, src + r * 512 + c * 16);
            }
            CP_COMMIT();
        }

        const uint32_t TsB = bufA[i % 3] + bThread;

        float acc[8][4];
#pragma unroll
        for (int nt = 0; nt < 8; nt++)
#pragma unroll
            for (int j = 0; j < 4; j++) acc[nt][j] = 0.f;

#pragma unroll
        for (int ks = 0; ks < 16; ks++) {
            const uint32_t kOff = (uint32_t)(ks * 32);
#pragma unroll
            for (int np = 0; np < 4; np++) {    // 16 n-rows per ldmatrix x4
                uint32_t b0, b1, b2, b3;
                uint32_t addr = TsB + (uint32_t)(np * 16 * LDS_ROW * 2) + kOff;
                asm volatile("ldmatrix.sync.aligned.m8n8.x4.shared.b16 {%0,%1,%2,%3}, [%4];"
                             : "=r"(b0), "=r"(b1), "=r"(b2), "=r"(b3)
                             : "r"(addr));
                asm volatile(
                    "mma.sync.aligned.m16n8k16.row.col.f32.bf16.bf16.f32 "
                    "{%0,%1,%2,%3}, {%4,%5,%6,%7}, {%8,%9}, {%0,%1,%2,%3};"
                    : "+f"(acc[2*np][0]), "+f"(acc[2*np][1]),
                      "+f"(acc[2*np][2]), "+f"(acc[2*np][3])
                    : "r"(Areg[ks][0]), "r"(Areg[ks][1]),
                      "r"(Areg[ks][2]), "r"(Areg[ks][3]),
                      "r"(b0), "r"(b1));
                asm volatile(
                    "mma.sync.aligned.m16n8k16.row.col.f32.bf16.bf16.f32 "
                    "{%0,%1,%2,%3}, {%4,%5,%6,%7}, {%8,%9}, {%0,%1,%2,%3};"
                    : "+f"(acc[2*np+1][0]), "+f"(acc[2*np+1][1]),
                      "+f"(acc[2*np+1][2]), "+f"(acc[2*np+1][3])
                    : "r"(Areg[ks][0]), "r"(Areg[ks][1]),
                      "r"(Areg[ks][2]), "r"(Areg[ks][3]),
                      "r"(b2), "r"(b3));
            }
        }

        // Fused epilogue — no masking (pad rows handled analytically in finalize)
#pragma unroll
        for (int nt = 0; nt < 8; nt++)
#pragma unroll
            for (int j = 0; j < 4; j++) {
                float c  = acc[nt][j];
                float x  = fmaxf(fmaf(-2.f, c, 2.f), 0.f);
                float dd = fsqrt_ap(x);
                float e  = fex2_ap(dd * -14.4269504089f);   // exp(-10*d)
                int   h  = j >> 1;
                lrow[h] += e;
                srow[h]  = fmaf(e, dd, srow[h]);
            }
    }

    // Reduce across the 4 lanes sharing a row; each row owned by exactly one warp
#pragma unroll
    for (int h = 0; h < 2; h++) {
        float lv = lrow[h], sv = srow[h];
        lv += __shfl_xor_sync(0xffffffffu, lv, 1);
        lv += __shfl_xor_sync(0xffffffffu, lv, 2);
        sv += __shfl_xor_sync(0xffffffffu, sv, 1);
        sv += __shfl_xor_sync(0xffffffffu, sv, 2);
        if ((lane & 3) == 0) {
            int r = qbase + wm * 16 + (lane >> 2) + 8 * h;
            atomicAdd(&g_l[r], lv);
            atomicAdd(&g_s[r], sv);
        }
    }
}

__global__ void finalize_kernel(float* __restrict__ out, int B, int padCount) {
    int i = blockIdx.x * blockDim.x + threadIdx.x;
    if (i >= B) return;
    // pad rows contribute c=0 -> d0 = sqrt.approx(2), e0 = ex2.approx(-10*d0*log2e)
    float d0 = fsqrt_ap(2.0f);
    float e0 = fex2_ap(d0 * -14.4269504089f);
    float fp = (float)padCount;
    out[i] = (g_s[i] - fp * e0 * d0) / (g_l[i] - fp * e0);
}

// ---------------- launch ----------------

extern "C" void kernel_launch(void* const* d_in, const int* in_sizes, int n_in,
                              void* d_out, int out_size) {
    const float* q = (const float*)d_in[0];
    const float* t = (const float*)d_in[1];
    int B = in_sizes[0] / D;
    int N = in_sizes[1] / D;
    if (B > MAXB) B = MAXB;
    int Npad = ((N + BNT - 1) / BNT) * BNT;
    if (Npad > MAXN_PAD) Npad = MAXN_PAD;
    int tilesTotal = Npad / BNT;
    int padCount = tilesTotal * BNT - N;

    const int smemBytes = 3 * BUF_BYTES;
    cudaFuncSetAttribute(knn_main_kernel,
                         cudaFuncAttributeMaxDynamicSharedMemorySize, smemBytes);

    prep_q_kernel<<<(B * 32 + 255) / 256, 256>>>(q, B);
    prep_t_kernel<<<(Npad * 32 + 255) / 256, 256>>>(t, N, Npad);

    int numQB = B / BM;
    if (numQB < 1) numQB = 1;
    knn_main_kernel<<<dim3(numQB, NSPLIT), NTHREADS, smemBytes>>>(tilesTotal);

    finalize_kernel<<<(B + 255) / 256, 256>>>((float*)d_out, B, padCount);
}